// round 13
// baseline (speedup 1.0000x reference)
#include <cuda_runtime.h>
#include <cuda_fp16.h>
#include <cstdint>
#include <cstring>

#define FEAT   40
#define EDIM   64
#define ADIM   64
#define NB     9            // n-blocks: 8 for W (64 cols) + 1 for pw column
#define NPAIR  780          // FEAT*(FEAT-1)/2
#define NT     256
#define TILE_P 128          // pairs per tile (8 warps x 16)
#define NTILES 7            // ceil(780/128)
#define XS_STRIDE 68        // padded x row
#define NFRAG  (4 * NB * 32)

// ---------------------------------------------------------------------------
// m16n8k16 fp16 MMA with f32 accumulation (arch-generic, works on sm_100)
// ---------------------------------------------------------------------------
__device__ __forceinline__ void mma_fp16(float d[4],
                                         uint32_t a0, uint32_t a1,
                                         uint32_t a2, uint32_t a3,
                                         uint32_t b0, uint32_t b1) {
    asm volatile(
        "mma.sync.aligned.m16n8k16.row.col.f32.f16.f16.f32 "
        "{%0,%1,%2,%3}, {%4,%5,%6,%7}, {%8,%9}, {%0,%1,%2,%3};"
        : "+f"(d[0]), "+f"(d[1]), "+f"(d[2]), "+f"(d[3])
        : "r"(a0), "r"(a1), "r"(a2), "r"(a3), "r"(b0), "r"(b1));
}

__device__ __forceinline__ uint32_t h2u(__half2 h) {
    uint32_t u;
    memcpy(&u, &h, 4);
    return u;
}

// Precomputed W' fragments (single fp16) + pair table, built once.
__device__ uint2 g_Whf[NFRAG];
__device__ unsigned char g_pii[800];          // padded to 16B multiple
__device__ unsigned char g_pjj[800];

__global__ void prep_kernel(const float* __restrict__ W,
                            const float* __restrict__ pw) {
    // W' = [W | pw | 0...]: per (eblk, nblk, lane):
    //   n = 8*nblk + lane/4 ; k0 = 16*eblk + (lane%4)*2
    for (int idx = threadIdx.x; idx < NFRAG; idx += 288) {
        int l    = idx & 31;
        int nblk = (idx >> 5) % NB;
        int eblk = (idx >> 5) / NB;
        int n  = 8 * nblk + (l >> 2);
        int k0 = 16 * eblk + (l & 3) * 2;
        float w00, w01, w10, w11;
        if (n < ADIM) {
            w00 = W[(k0    ) * ADIM + n];
            w01 = W[(k0 + 1) * ADIM + n];
            w10 = W[(k0 + 8) * ADIM + n];
            w11 = W[(k0 + 9) * ADIM + n];
        } else if (n == ADIM) {           // the pw column
            w00 = pw[k0];     w01 = pw[k0 + 1];
            w10 = pw[k0 + 8]; w11 = pw[k0 + 9];
        } else {                           // zero padding cols 65..71
            w00 = w01 = w10 = w11 = 0.f;
        }
        g_Whf[idx] = make_uint2(h2u(__floats2half2_rn(w00, w01)),
                                h2u(__floats2half2_rn(w10, w11)));
    }
    // pair table (triu order)
    if (threadIdx.x < FEAT - 1) {
        int i = threadIdx.x;
        int base = i * (FEAT - 1) - i * (i - 1) / 2;
        for (int j = i + 1; j < FEAT; j++) {
            g_pii[base + j - i - 1] = (unsigned char)i;
            g_pjj[base + j - i - 1] = (unsigned char)j;
        }
    }
}

struct __align__(16) Smem {
    float xs[FEAT * XS_STRIDE];   // 10880  e-PERMUTED x rows
    uint2 Whf[NFRAG];             // 9216   W' fragments [eblk][nblk][lane]
    float sc[NPAIR];              // 3120   scores
    float sq[NPAIR];              // 3120   q_p = BI_p . pw
    float bs[ADIM];
    float hs[ADIM];
    float redm[8];
    float reds[8];
    float redd[8];
    unsigned char pii[800];
    unsigned char pjj[800];
};

__global__ __launch_bounds__(NT, 3)
void afm_main_kernel(const float* __restrict__ x,
                     const float* __restrict__ bias,
                     const float* __restrict__ h,
                     float* __restrict__ out) {
    extern __shared__ char smem_raw[];
    Smem* s = reinterpret_cast<Smem*>(smem_raw);

    const int b    = blockIdx.x;
    const int tid  = threadIdx.x;
    const int wid  = tid >> 5;
    const int lane = tid & 31;

    // ---------------- Phase 0: coalesced staging (xs e-permuted) --------
    // perm within each 16-col block: e = 8h + 2t + s  ->  4t + 2h + s
    // so a thread's four k-values {k0,k0+1,k0+8,k0+9} become one float4.
    {
        const float* xb = x + (long)b * FEAT * EDIM;
        for (int idx = tid; idx < FEAT * EDIM; idx += NT) {
            int row = idx >> 6, col = idx & 63;
            int bl = col & 15;
            int newb = ((bl & 6) << 1) | ((bl >> 3) << 1) | (bl & 1);
            s->xs[row * XS_STRIDE + (col & ~15) + newb] = xb[idx];
        }
        const uint4* src = (const uint4*)g_Whf;     // 9216 B = 576 uint4
        uint4* dst = (uint4*)s->Whf;
        for (int i = tid; i < 576; i += NT) dst[i] = src[i];
        {   // pair tables: 2 x 50 uint4
            const uint4* pi = (const uint4*)g_pii;
            const uint4* pj = (const uint4*)g_pjj;
            uint4* di = (uint4*)s->pii;
            uint4* dj = (uint4*)s->pjj;
            if (tid < 50) di[tid] = pi[tid];
            else if (tid < 100) dj[tid - 50] = pj[tid - 50];
        }
        if (tid < ADIM) { s->bs[tid] = bias[tid]; s->hs[tid] = h[tid]; }
    }
    __syncthreads();

    const int r  = lane >> 2;          // row-within-16 (0..7)
    const int c0 = (lane & 3) * 2;     // col pair base (epilogue)
    const int t4 = (lane & 3) * 4;     // permuted k-group offset (A-build)

    // ---------------- Phase 1: one m16 block per warp-tile --------------
    for (int tile = 0; tile < NTILES; tile++) {
        const int pbase = tile * TILE_P + wid * 16;
        if (pbase >= NPAIR) continue;

        const int p0 = pbase + r;
        const int p1 = pbase + r + 8;
        const int i0 = (p0 < NPAIR) ? s->pii[p0] : 0;
        const int j0 = (p0 < NPAIR) ? s->pjj[p0] : 0;
        const int i1 = (p1 < NPAIR) ? s->pii[p1] : 0;
        const int j1 = (p1 < NPAIR) ? s->pjj[p1] : 0;
        const int oI0 = i0 * XS_STRIDE, oJ0 = j0 * XS_STRIDE;
        const int oI1 = i1 * XS_STRIDE, oJ1 = j1 * XS_STRIDE;

        // D accumulators: d[nb][4]; bias for nb<8, zero for the q column
        float d[NB][4];
        #pragma unroll
        for (int ab = 0; ab < 8; ab++) {
            float b0v = s->bs[8 * ab + c0];
            float b1v = s->bs[8 * ab + c0 + 1];
            d[ab][0] = b0v; d[ab][1] = b1v;
            d[ab][2] = b0v; d[ab][3] = b1v;
        }
        d[8][0] = 0.f; d[8][1] = 0.f; d[8][2] = 0.f; d[8][3] = 0.f;

        #pragma unroll
        for (int eb = 0; eb < 4; eb++) {
            const int e4 = 16 * eb + t4;
            // --- A fragments via permuted float4 loads: 4 LDS.128 total ---
            uint32_t a0, a1, a2, a3;
            {
                float4 xi = *(const float4*)(s->xs + oI0 + e4);
                float4 xj = *(const float4*)(s->xs + oJ0 + e4);
                a0 = h2u(__floats2half2_rn(xi.x * xj.x, xi.y * xj.y));
                a2 = h2u(__floats2half2_rn(xi.z * xj.z, xi.w * xj.w));
            }
            {
                float4 xi = *(const float4*)(s->xs + oI1 + e4);
                float4 xj = *(const float4*)(s->xs + oJ1 + e4);
                a1 = h2u(__floats2half2_rn(xi.x * xj.x, xi.y * xj.y));
                a3 = h2u(__floats2half2_rn(xi.z * xj.z, xi.w * xj.w));
            }

            // --- one LDS.64 + one MMA per n-block ---
            #pragma unroll
            for (int ab = 0; ab < NB; ab++) {
                uint2 bf = s->Whf[(eb * NB + ab) * 32 + lane];
                mma_fp16(d[ab], a0, a1, a2, a3, bf.x, bf.y);
            }
        }

        // --- epilogue: relu(z)·h reduce, plus direct q extraction ---
        float s0 = 0.f, s1 = 0.f;
        #pragma unroll
        for (int ab = 0; ab < 8; ab++) {
            int a = 8 * ab + c0;
            float h0v = s->hs[a], h1v = s->hs[a + 1];
            s0 = fmaf(fmaxf(d[ab][0], 0.f), h0v, s0);
            s0 = fmaf(fmaxf(d[ab][1], 0.f), h1v, s0);
            s1 = fmaf(fmaxf(d[ab][2], 0.f), h0v, s1);
            s1 = fmaf(fmaxf(d[ab][3], 0.f), h1v, s1);
        }
        s0 += __shfl_xor_sync(0xffffffffu, s0, 1);
        s0 += __shfl_xor_sync(0xffffffffu, s0, 2);
        s1 += __shfl_xor_sync(0xffffffffu, s1, 1);
        s1 += __shfl_xor_sync(0xffffffffu, s1, 2);
        if ((lane & 3) == 0) {
            if (p0 < NPAIR) { s->sc[p0] = s0; s->sq[p0] = d[8][0]; }
            if (p1 < NPAIR) { s->sc[p1] = s1; s->sq[p1] = d[8][2]; }
        }
    }
    __syncthreads();

    // ---------------- Phase 2: fused softmax + weighted dot -------------
    float m = -3.402823466e38f;
    for (int p = tid; p < NPAIR; p += NT) m = fmaxf(m, s->sc[p]);
    #pragma unroll
    for (int o = 16; o; o >>= 1) m = fmaxf(m, __shfl_xor_sync(0xffffffffu, m, o));
    if (lane == 0) s->redm[wid] = m;
    __syncthreads();
    if (tid == 0) {
        float mm = s->redm[0];
        #pragma unroll
        for (int w = 1; w < 8; w++) mm = fmaxf(mm, s->redm[w]);
        s->redm[0] = mm;
    }
    __syncthreads();
    m = s->redm[0];

    float sum = 0.f, dot = 0.f;
    for (int p = tid; p < NPAIR; p += NT) {
        float e0 = __expf(s->sc[p] - m);
        sum += e0;
        dot = fmaf(e0, s->sq[p], dot);
    }
    #pragma unroll
    for (int o = 16; o; o >>= 1) {
        sum += __shfl_xor_sync(0xffffffffu, sum, o);
        dot += __shfl_xor_sync(0xffffffffu, dot, o);
    }
    if (lane == 0) { s->reds[wid] = sum; s->redd[wid] = dot; }
    __syncthreads();
    if (tid == 0) {
        float ss = s->reds[0], dd = s->redd[0];
        #pragma unroll
        for (int w = 1; w < 8; w++) { ss += s->reds[w]; dd += s->redd[w]; }
        out[b] = (float)NPAIR * dd / ss;
    }
}

extern "C" void kernel_launch(void* const* d_in, const int* in_sizes, int n_in,
                              void* d_out, int out_size) {
    const float* x    = (const float*)d_in[0];
    const float* W    = (const float*)d_in[1];
    const float* bias = (const float*)d_in[2];
    const float* h    = (const float*)d_in[3];
    const float* pw   = (const float*)d_in[4];
    float* out = (float*)d_out;

    int B = in_sizes[0] / (FEAT * EDIM);
    size_t smem_bytes = sizeof(Smem);

    static bool attr_set = false;
    if (!attr_set) {
        cudaFuncSetAttribute(afm_main_kernel,
                             cudaFuncAttributeMaxDynamicSharedMemorySize,
                             (int)smem_bytes);
        attr_set = true;
    }

    prep_kernel<<<1, 288>>>(W, pw);
    afm_main_kernel<<<B, NT, smem_bytes>>>(x, bias, h, out);
}

// round 14
// speedup vs baseline: 1.0621x; 1.0621x over previous
#include <cuda_runtime.h>
#include <cuda_fp16.h>
#include <cstdint>
#include <cstring>

#define FEAT   40
#define EDIM   64
#define ADIM   64
#define NB     9            // n-blocks: 8 for W (64 cols) + 1 for pw column
#define NPAIR  780
#define NSLOT  784          // 49 blocks x 16 slots (4 dummies)
#define NBLK   49
#define NT     256
#define NTILES 7            // ceil(49/8)
#define XS_STRIDE 80        // row stride: 80 mod 32 = 16 banks -> adjacent rows disjoint
#define NFRAG  (4 * NB * 32)

// ---------------------------------------------------------------------------
// m16n8k16 fp16 MMA with f32 accumulation (arch-generic, works on sm_100)
// ---------------------------------------------------------------------------
__device__ __forceinline__ void mma_fp16(float d[4],
                                         uint32_t a0, uint32_t a1,
                                         uint32_t a2, uint32_t a3,
                                         uint32_t b0, uint32_t b1) {
    asm volatile(
        "mma.sync.aligned.m16n8k16.row.col.f32.f16.f16.f32 "
        "{%0,%1,%2,%3}, {%4,%5,%6,%7}, {%8,%9}, {%0,%1,%2,%3};"
        : "+f"(d[0]), "+f"(d[1]), "+f"(d[2]), "+f"(d[3])
        : "r"(a0), "r"(a1), "r"(a2), "r"(a3), "r"(b0), "r"(b1));
}

__device__ __forceinline__ uint32_t h2u(__half2 h) {
    uint32_t u;
    memcpy(&u, &h, 4);
    return u;
}

// Precomputed W' fragments + grid-blocked slot->(i,j) tables, built once.
__device__ uint2 g_Whf[NFRAG];
__device__ unsigned char g_bi[800];
__device__ unsigned char g_bj[800];

__global__ void prep_kernel(const float* __restrict__ W,
                            const float* __restrict__ pw) {
    // W' = [W | pw | 0...]: per (eblk, nblk, lane):
    //   n = 8*nblk + lane/4 ; k0 = 16*eblk + (lane%4)*2
    for (int idx = threadIdx.x; idx < NFRAG; idx += 288) {
        int l    = idx & 31;
        int nblk = (idx >> 5) % NB;
        int eblk = (idx >> 5) / NB;
        int n  = 8 * nblk + (l >> 2);
        int k0 = 16 * eblk + (l & 3) * 2;
        float w00, w01, w10, w11;
        if (n < ADIM) {
            w00 = W[(k0    ) * ADIM + n];
            w01 = W[(k0 + 1) * ADIM + n];
            w10 = W[(k0 + 8) * ADIM + n];
            w11 = W[(k0 + 9) * ADIM + n];
        } else if (n == ADIM) {           // the pw column
            w00 = pw[k0];     w01 = pw[k0 + 1];
            w10 = pw[k0 + 8]; w11 = pw[k0 + 9];
        } else {                           // zero padding cols 65..71
            w00 = w01 = w10 = w11 = 0.f;
        }
        g_Whf[idx] = make_uint2(h2u(__floats2half2_rn(w00, w01)),
                                h2u(__floats2half2_rn(w10, w11)));
    }
    // Grid-blocked pair tables: 45 cross blocks (4x4 grids) + intra pairs.
    if (threadIdx.x == 0) {
        int t = 0;
        for (int g0 = 0; g0 < 10; g0++)
            for (int g1 = g0 + 1; g1 < 10; g1++) {
                for (int q = 0; q < 16; q++) {
                    g_bi[t] = (unsigned char)(4 * g0 + (q >> 2));
                    g_bj[t] = (unsigned char)(4 * g1 + (q & 3));
                    t++;
                }
            }
        for (int g = 0; g < 10; g++)
            for (int a = 0; a < 4; a++)
                for (int c = a + 1; c < 4; c++) {
                    g_bi[t] = (unsigned char)(4 * g + a);
                    g_bj[t] = (unsigned char)(4 * g + c);
                    t++;
                }
        for (; t < 800; t++) { g_bi[t] = 255; g_bj[t] = 0; }
    }
}

struct __align__(16) Smem {
    float xs[FEAT * XS_STRIDE];   // 12800  e-PERMUTED x rows
    uint2 Whf[NFRAG];             // 9216   W' fragments [eblk][nblk][lane]
    float sc[NSLOT];              // 3136   scores (slot order)
    float sq[NSLOT];              // 3136   q_p = BI_p . pw
    float bs[ADIM];
    float hs[ADIM];
    float redm[8];
    float reds[8];
    float redd[8];
    unsigned char bi[800];
    unsigned char bj[800];
};

__global__ __launch_bounds__(NT, 4)
void afm_main_kernel(const float* __restrict__ x,
                     const float* __restrict__ bias,
                     const float* __restrict__ h,
                     float* __restrict__ out) {
    extern __shared__ char smem_raw[];
    Smem* s = reinterpret_cast<Smem*>(smem_raw);

    const int b    = blockIdx.x;
    const int tid  = threadIdx.x;
    const int wid  = tid >> 5;
    const int lane = tid & 31;

    // ---------------- Phase 0: coalesced staging (xs e-permuted) --------
    // perm within each 16-col block: e = 8h + 2t + s  ->  4t + 2h + s
    {
        const float* xb = x + (long)b * FEAT * EDIM;
        for (int idx = tid; idx < FEAT * EDIM; idx += NT) {
            int row = idx >> 6, col = idx & 63;
            int bl = col & 15;
            int newb = ((bl & 6) << 1) | ((bl >> 3) << 1) | (bl & 1);
            s->xs[row * XS_STRIDE + (col & ~15) + newb] = xb[idx];
        }
        const uint4* src = (const uint4*)g_Whf;     // 9216 B = 576 uint4
        uint4* dst = (uint4*)s->Whf;
        for (int i = tid; i < 576; i += NT) dst[i] = src[i];
        {   // slot tables: 2 x 50 uint4
            const uint4* pi = (const uint4*)g_bi;
            const uint4* pj = (const uint4*)g_bj;
            uint4* di = (uint4*)s->bi;
            uint4* dj = (uint4*)s->bj;
            if (tid < 50) di[tid] = pi[tid];
            else if (tid < 100) dj[tid - 50] = pj[tid - 50];
        }
        if (tid < ADIM) { s->bs[tid] = bias[tid]; s->hs[tid] = h[tid]; }
    }
    __syncthreads();

    const int r  = lane >> 2;          // row-within-16 (0..7)
    const int c0 = (lane & 3) * 2;     // col pair base (epilogue)
    const int t4 = (lane & 3) * 4;     // permuted k-group offset (A-build)

    // ---------------- Phase 1: one m16 grid-block per warp-tile ---------
    for (int tile = 0; tile < NTILES; tile++) {
        const int blk = tile * 8 + wid;
        if (blk >= NBLK) continue;
        const int slot0 = blk * 16;

        const int iv0 = s->bi[slot0 + r];
        const int jv0 = s->bj[slot0 + r];
        const int iv1 = s->bi[slot0 + r + 8];
        const int jv1 = s->bj[slot0 + r + 8];
        const bool v0 = (iv0 != 255);
        const bool v1 = (iv1 != 255);
        const int oI0 = (v0 ? iv0 : 0) * XS_STRIDE;
        const int oJ0 = jv0 * XS_STRIDE;
        const int oI1 = (v1 ? iv1 : 0) * XS_STRIDE;
        const int oJ1 = jv1 * XS_STRIDE;

        // D accumulators: d[nb][4]; bias for nb<8, zero for the q column
        float d[NB][4];
        #pragma unroll
        for (int ab = 0; ab < 8; ab++) {
            float b0v = s->bs[8 * ab + c0];
            float b1v = s->bs[8 * ab + c0 + 1];
            d[ab][0] = b0v; d[ab][1] = b1v;
            d[ab][2] = b0v; d[ab][3] = b1v;
        }
        d[8][0] = 0.f; d[8][1] = 0.f; d[8][2] = 0.f; d[8][3] = 0.f;

        #pragma unroll
        for (int eb = 0; eb < 4; eb++) {
            const int e4 = 16 * eb + t4;
            // A fragments: xi spans 2 rows (1 LDS cyc), xj 4 rows (2 cyc)
            uint32_t a0, a1, a2, a3;
            {
                float4 xi = *(const float4*)(s->xs + oI0 + e4);
                float4 xj = *(const float4*)(s->xs + oJ0 + e4);
                a0 = h2u(__floats2half2_rn(xi.x * xj.x, xi.y * xj.y));
                a2 = h2u(__floats2half2_rn(xi.z * xj.z, xi.w * xj.w));
            }
            {
                float4 xi = *(const float4*)(s->xs + oI1 + e4);
                float4 xj = *(const float4*)(s->xs + oJ1 + e4);
                a1 = h2u(__floats2half2_rn(xi.x * xj.x, xi.y * xj.y));
                a3 = h2u(__floats2half2_rn(xi.z * xj.z, xi.w * xj.w));
            }

            // one LDS.64 + one MMA per n-block
            #pragma unroll
            for (int ab = 0; ab < NB; ab++) {
                uint2 bf = s->Whf[(eb * NB + ab) * 32 + lane];
                mma_fp16(d[ab], a0, a1, a2, a3, bf.x, bf.y);
            }
        }

        // --- epilogue: relu(z)·h reduce, plus direct q extraction ---
        float s0 = 0.f, s1 = 0.f;
        #pragma unroll
        for (int ab = 0; ab < 8; ab++) {
            int a = 8 * ab + c0;
            float h0v = s->hs[a], h1v = s->hs[a + 1];
            s0 = fmaf(fmaxf(d[ab][0], 0.f), h0v, s0);
            s0 = fmaf(fmaxf(d[ab][1], 0.f), h1v, s0);
            s1 = fmaf(fmaxf(d[ab][2], 0.f), h0v, s1);
            s1 = fmaf(fmaxf(d[ab][3], 0.f), h1v, s1);
        }
        s0 += __shfl_xor_sync(0xffffffffu, s0, 1);
        s0 += __shfl_xor_sync(0xffffffffu, s0, 2);
        s1 += __shfl_xor_sync(0xffffffffu, s1, 1);
        s1 += __shfl_xor_sync(0xffffffffu, s1, 2);
        if ((lane & 3) == 0) {
            s->sc[slot0 + r]     = v0 ? s0 : -1e30f;
            s->sq[slot0 + r]     = v0 ? d[8][0] : 0.f;
            s->sc[slot0 + r + 8] = v1 ? s1 : -1e30f;
            s->sq[slot0 + r + 8] = v1 ? d[8][2] : 0.f;
        }
    }
    __syncthreads();

    // ---------------- Phase 2: fused softmax + weighted dot -------------
    float m = -3.402823466e38f;
    for (int p = tid; p < NSLOT; p += NT) m = fmaxf(m, s->sc[p]);
    #pragma unroll
    for (int o = 16; o; o >>= 1) m = fmaxf(m, __shfl_xor_sync(0xffffffffu, m, o));
    if (lane == 0) s->redm[wid] = m;
    __syncthreads();
    if (tid == 0) {
        float mm = s->redm[0];
        #pragma unroll
        for (int w = 1; w < 8; w++) mm = fmaxf(mm, s->redm[w]);
        s->redm[0] = mm;
    }
    __syncthreads();
    m = s->redm[0];

    float sum = 0.f, dot = 0.f;
    for (int p = tid; p < NSLOT; p += NT) {
        float e0 = __expf(s->sc[p] - m);      // dummies: exp(-1e30-m) = 0
        sum += e0;
        dot = fmaf(e0, s->sq[p], dot);
    }
    #pragma unroll
    for (int o = 16; o; o >>= 1) {
        sum += __shfl_xor_sync(0xffffffffu, sum, o);
        dot += __shfl_xor_sync(0xffffffffu, dot, o);
    }
    if (lane == 0) { s->reds[wid] = sum; s->redd[wid] = dot; }
    __syncthreads();
    if (tid == 0) {
        float ss = s->reds[0], dd = s->redd[0];
        #pragma unroll
        for (int w = 1; w < 8; w++) { ss += s->reds[w]; dd += s->redd[w]; }
        out[b] = (float)NPAIR * dd / ss;
    }
}

extern "C" void kernel_launch(void* const* d_in, const int* in_sizes, int n_in,
                              void* d_out, int out_size) {
    const float* x    = (const float*)d_in[0];
    const float* W    = (const float*)d_in[1];
    const float* bias = (const float*)d_in[2];
    const float* h    = (const float*)d_in[3];
    const float* pw   = (const float*)d_in[4];
    float* out = (float*)d_out;

    int B = in_sizes[0] / (FEAT * EDIM);
    size_t smem_bytes = sizeof(Smem);

    static bool attr_set = false;
    if (!attr_set) {
        cudaFuncSetAttribute(afm_main_kernel,
                             cudaFuncAttributeMaxDynamicSharedMemorySize,
                             (int)smem_bytes);
        attr_set = true;
    }

    prep_kernel<<<1, 288>>>(W, pw);
    afm_main_kernel<<<B, NT, smem_bytes>>>(x, bias, h, out);
}

// round 15
// speedup vs baseline: 1.2319x; 1.1599x over previous
#include <cuda_runtime.h>
#include <cuda_fp16.h>
#include <cstdint>
#include <cstring>

#define FEAT   40
#define EDIM   64
#define ADIM   64
#define NB     9            // n-blocks: 8 for W (64 cols) + 1 for pw column
#define NPAIR  780
#define NBLK2  50           // padded block count (pairs of blocks per warp)
#define NSLOT  800          // 50 blocks x 16 slots
#define NPTILE 25           // block-pairs
#define NT     256
#define XS_STRIDE 80        // adjacent rows bank-disjoint
#define NFRAG  (4 * NB * 32)

// ---------------------------------------------------------------------------
// m16n8k16 fp16 MMA with f32 accumulation (arch-generic, works on sm_100)
// ---------------------------------------------------------------------------
__device__ __forceinline__ void mma_fp16(float d[4],
                                         uint32_t a0, uint32_t a1,
                                         uint32_t a2, uint32_t a3,
                                         uint32_t b0, uint32_t b1) {
    asm volatile(
        "mma.sync.aligned.m16n8k16.row.col.f32.f16.f16.f32 "
        "{%0,%1,%2,%3}, {%4,%5,%6,%7}, {%8,%9}, {%0,%1,%2,%3};"
        : "+f"(d[0]), "+f"(d[1]), "+f"(d[2]), "+f"(d[3])
        : "r"(a0), "r"(a1), "r"(a2), "r"(a3), "r"(b0), "r"(b1));
}

__device__ __forceinline__ uint32_t h2u(__half2 h) {
    uint32_t u;
    memcpy(&u, &h, 4);
    return u;
}

// Precomputed W' fragments + grid-blocked slot->(i,j) tables, built once.
__device__ uint2 g_Whf[NFRAG];
__device__ unsigned char g_bi[NSLOT];
__device__ unsigned char g_bj[NSLOT];

__global__ void prep_kernel(const float* __restrict__ W,
                            const float* __restrict__ pw) {
    for (int idx = threadIdx.x; idx < NFRAG; idx += 288) {
        int l    = idx & 31;
        int nblk = (idx >> 5) % NB;
        int eblk = (idx >> 5) / NB;
        int n  = 8 * nblk + (l >> 2);
        int k0 = 16 * eblk + (l & 3) * 2;
        float w00, w01, w10, w11;
        if (n < ADIM) {
            w00 = W[(k0    ) * ADIM + n];
            w01 = W[(k0 + 1) * ADIM + n];
            w10 = W[(k0 + 8) * ADIM + n];
            w11 = W[(k0 + 9) * ADIM + n];
        } else if (n == ADIM) {           // the pw column
            w00 = pw[k0];     w01 = pw[k0 + 1];
            w10 = pw[k0 + 8]; w11 = pw[k0 + 9];
        } else {                           // zero padding cols 65..71
            w00 = w01 = w10 = w11 = 0.f;
        }
        g_Whf[idx] = make_uint2(h2u(__floats2half2_rn(w00, w01)),
                                h2u(__floats2half2_rn(w10, w11)));
    }
    // Grid-blocked pair tables: 45 cross blocks (4x4) + intra pairs; 255 = dummy
    if (threadIdx.x == 0) {
        int t = 0;
        for (int g0 = 0; g0 < 10; g0++)
            for (int g1 = g0 + 1; g1 < 10; g1++)
                for (int q = 0; q < 16; q++) {
                    g_bi[t] = (unsigned char)(4 * g0 + (q >> 2));
                    g_bj[t] = (unsigned char)(4 * g1 + (q & 3));
                    t++;
                }
        for (int g = 0; g < 10; g++)
            for (int a = 0; a < 4; a++)
                for (int c = a + 1; c < 4; c++) {
                    g_bi[t] = (unsigned char)(4 * g + a);
                    g_bj[t] = (unsigned char)(4 * g + c);
                    t++;
                }
        for (; t < NSLOT; t++) { g_bi[t] = 255; g_bj[t] = 0; }
    }
}

struct __align__(16) Smem {
    float xs[FEAT * XS_STRIDE];   // 12800  e-PERMUTED x rows
    uint2 Whf[NFRAG];             // 9216
    float sc[NSLOT];              // 3200
    float sq[NSLOT];              // 3200
    float bs[ADIM];
    float hs[ADIM];
    float redm[8];
    float reds[8];
    float redd[8];
    unsigned char bi[NSLOT];
    unsigned char bj[NSLOT];
};

__global__ __launch_bounds__(NT, 4)
void afm_main_kernel(const float* __restrict__ x,
                     const float* __restrict__ bias,
                     const float* __restrict__ h,
                     float* __restrict__ out) {
    extern __shared__ char smem_raw[];
    Smem* s = reinterpret_cast<Smem*>(smem_raw);

    const int b    = blockIdx.x;
    const int tid  = threadIdx.x;
    const int wid  = tid >> 5;
    const int lane = tid & 31;

    // ---------------- Phase 0: coalesced staging (xs e-permuted) --------
    {
        const float* xb = x + (long)b * FEAT * EDIM;
        for (int idx = tid; idx < FEAT * EDIM; idx += NT) {
            int row = idx >> 6, col = idx & 63;
            int bl = col & 15;
            int newb = ((bl & 6) << 1) | ((bl >> 3) << 1) | (bl & 1);
            s->xs[row * XS_STRIDE + (col & ~15) + newb] = xb[idx];
        }
        const uint4* src = (const uint4*)g_Whf;     // 576 uint4
        uint4* dst = (uint4*)s->Whf;
        for (int i = tid; i < 576; i += NT) dst[i] = src[i];
        {   // slot tables: 2 x 50 uint4
            const uint4* pi = (const uint4*)g_bi;
            const uint4* pj = (const uint4*)g_bj;
            uint4* di = (uint4*)s->bi;
            uint4* dj = (uint4*)s->bj;
            if (tid < 50) di[tid] = pi[tid];
            else if (tid < 100) dj[tid - 50] = pj[tid - 50];
        }
        if (tid < ADIM) { s->bs[tid] = bias[tid]; s->hs[tid] = h[tid]; }
    }
    __syncthreads();

    const int r  = lane >> 2;          // row-within-16 (0..7)
    const int c0 = (lane & 3) * 2;     // col pair base (epilogue)
    const int t4 = (lane & 3) * 4;     // permuted k-group offset (A-build)

    // ---------------- Phase 1: TWO m16 blocks per warp-tile --------------
    // nb-outer / eb-inner: accumulators are 8 regs; A frags held for both
    // blocks (32 regs); every B fragment feeds 2 MMAs.
    for (int pt = wid; pt < NPTILE; pt += 8) {
        const int slotA = (2 * pt)     * 16;
        const int slotB = (2 * pt + 1) * 16;

        const int ivA0 = s->bi[slotA + r],     jvA0 = s->bj[slotA + r];
        const int ivA1 = s->bi[slotA + r + 8], jvA1 = s->bj[slotA + r + 8];
        const int ivB0 = s->bi[slotB + r],     jvB0 = s->bj[slotB + r];
        const int ivB1 = s->bi[slotB + r + 8], jvB1 = s->bj[slotB + r + 8];
        const bool vA0 = (ivA0 != 255), vA1 = (ivA1 != 255);
        const bool vB0 = (ivB0 != 255), vB1 = (ivB1 != 255);
        const int oIA0 = (vA0 ? ivA0 : 0) * XS_STRIDE, oJA0 = jvA0 * XS_STRIDE;
        const int oIA1 = (vA1 ? ivA1 : 0) * XS_STRIDE, oJA1 = jvA1 * XS_STRIDE;
        const int oIB0 = (vB0 ? ivB0 : 0) * XS_STRIDE, oJB0 = jvB0 * XS_STRIDE;
        const int oIB1 = (vB1 ? ivB1 : 0) * XS_STRIDE, oJB1 = jvB1 * XS_STRIDE;

        // --- build A fragments for BOTH blocks, all 4 eb ---
        uint32_t aA[4][4], aB[4][4];
        #pragma unroll
        for (int eb = 0; eb < 4; eb++) {
            const int e4 = 16 * eb + t4;
            {
                float4 xi = *(const float4*)(s->xs + oIA0 + e4);
                float4 xj = *(const float4*)(s->xs + oJA0 + e4);
                aA[eb][0] = h2u(__floats2half2_rn(xi.x * xj.x, xi.y * xj.y));
                aA[eb][2] = h2u(__floats2half2_rn(xi.z * xj.z, xi.w * xj.w));
            }
            {
                float4 xi = *(const float4*)(s->xs + oIA1 + e4);
                float4 xj = *(const float4*)(s->xs + oJA1 + e4);
                aA[eb][1] = h2u(__floats2half2_rn(xi.x * xj.x, xi.y * xj.y));
                aA[eb][3] = h2u(__floats2half2_rn(xi.z * xj.z, xi.w * xj.w));
            }
            {
                float4 xi = *(const float4*)(s->xs + oIB0 + e4);
                float4 xj = *(const float4*)(s->xs + oJB0 + e4);
                aB[eb][0] = h2u(__floats2half2_rn(xi.x * xj.x, xi.y * xj.y));
                aB[eb][2] = h2u(__floats2half2_rn(xi.z * xj.z, xi.w * xj.w));
            }
            {
                float4 xi = *(const float4*)(s->xs + oIB1 + e4);
                float4 xj = *(const float4*)(s->xs + oJB1 + e4);
                aB[eb][1] = h2u(__floats2half2_rn(xi.x * xj.x, xi.y * xj.y));
                aB[eb][3] = h2u(__floats2half2_rn(xi.z * xj.z, xi.w * xj.w));
            }
        }

        // --- nb-outer loop: 8-reg accumulators, fused per-nb epilogue ---
        float sA0 = 0.f, sA1 = 0.f, sB0 = 0.f, sB1 = 0.f;
        float qA0 = 0.f, qA1 = 0.f, qB0 = 0.f, qB1 = 0.f;
        #pragma unroll
        for (int nb = 0; nb < NB; nb++) {
            float b0v = 0.f, b1v = 0.f;
            if (nb < 8) { b0v = s->bs[8 * nb + c0]; b1v = s->bs[8 * nb + c0 + 1]; }
            float d0[4] = {b0v, b1v, b0v, b1v};
            float d1[4] = {b0v, b1v, b0v, b1v};
            #pragma unroll
            for (int eb = 0; eb < 4; eb++) {
                uint2 bf = s->Whf[(eb * NB + nb) * 32 + lane];
                mma_fp16(d0, aA[eb][0], aA[eb][1], aA[eb][2], aA[eb][3],
                         bf.x, bf.y);
                mma_fp16(d1, aB[eb][0], aB[eb][1], aB[eb][2], aB[eb][3],
                         bf.x, bf.y);
            }
            if (nb < 8) {
                float h0v = s->hs[8 * nb + c0], h1v = s->hs[8 * nb + c0 + 1];
                sA0 = fmaf(fmaxf(d0[0], 0.f), h0v, sA0);
                sA0 = fmaf(fmaxf(d0[1], 0.f), h1v, sA0);
                sA1 = fmaf(fmaxf(d0[2], 0.f), h0v, sA1);
                sA1 = fmaf(fmaxf(d0[3], 0.f), h1v, sA1);
                sB0 = fmaf(fmaxf(d1[0], 0.f), h0v, sB0);
                sB0 = fmaf(fmaxf(d1[1], 0.f), h1v, sB0);
                sB1 = fmaf(fmaxf(d1[2], 0.f), h0v, sB1);
                sB1 = fmaf(fmaxf(d1[3], 0.f), h1v, sB1);
            } else {
                qA0 = d0[0]; qA1 = d0[2];
                qB0 = d1[0]; qB1 = d1[2];
            }
        }

        // --- reduce 4 lanes per row, store scores + q ---
        sA0 += __shfl_xor_sync(0xffffffffu, sA0, 1);
        sA0 += __shfl_xor_sync(0xffffffffu, sA0, 2);
        sA1 += __shfl_xor_sync(0xffffffffu, sA1, 1);
        sA1 += __shfl_xor_sync(0xffffffffu, sA1, 2);
        sB0 += __shfl_xor_sync(0xffffffffu, sB0, 1);
        sB0 += __shfl_xor_sync(0xffffffffu, sB0, 2);
        sB1 += __shfl_xor_sync(0xffffffffu, sB1, 1);
        sB1 += __shfl_xor_sync(0xffffffffu, sB1, 2);
        if ((lane & 3) == 0) {
            s->sc[slotA + r]     = vA0 ? sA0 : -1e30f;
            s->sq[slotA + r]     = vA0 ? qA0 : 0.f;
            s->sc[slotA + r + 8] = vA1 ? sA1 : -1e30f;
            s->sq[slotA + r + 8] = vA1 ? qA1 : 0.f;
            s->sc[slotB + r]     = vB0 ? sB0 : -1e30f;
            s->sq[slotB + r]     = vB0 ? qB0 : 0.f;
            s->sc[slotB + r + 8] = vB1 ? sB1 : -1e30f;
            s->sq[slotB + r + 8] = vB1 ? qB1 : 0.f;
        }
    }
    __syncthreads();

    // ---------------- Phase 2: fused softmax + weighted dot -------------
    float m = -3.402823466e38f;
    for (int p = tid; p < NSLOT; p += NT) m = fmaxf(m, s->sc[p]);
    #pragma unroll
    for (int o = 16; o; o >>= 1) m = fmaxf(m, __shfl_xor_sync(0xffffffffu, m, o));
    if (lane == 0) s->redm[wid] = m;
    __syncthreads();
    if (tid == 0) {
        float mm = s->redm[0];
        #pragma unroll
        for (int w = 1; w < 8; w++) mm = fmaxf(mm, s->redm[w]);
        s->redm[0] = mm;
    }
    __syncthreads();
    m = s->redm[0];

    float sum = 0.f, dot = 0.f;
    for (int p = tid; p < NSLOT; p += NT) {
        float e0 = __expf(s->sc[p] - m);      // dummies -> 0
        sum += e0;
        dot = fmaf(e0, s->sq[p], dot);
    }
    #pragma unroll
    for (int o = 16; o; o >>= 1) {
        sum += __shfl_xor_sync(0xffffffffu, sum, o);
        dot += __shfl_xor_sync(0xffffffffu, dot, o);
    }
    if (lane == 0) { s->reds[wid] = sum; s->redd[wid] = dot; }
    __syncthreads();
    if (tid == 0) {
        float ss = s->reds[0], dd = s->redd[0];
        #pragma unroll
        for (int w = 1; w < 8; w++) { ss += s->reds[w]; dd += s->redd[w]; }
        out[b] = (float)NPAIR * dd / ss;
    }
}

extern "C" void kernel_launch(void* const* d_in, const int* in_sizes, int n_in,
                              void* d_out, int out_size) {
    const float* x    = (const float*)d_in[0];
    const float* W    = (const float*)d_in[1];
    const float* bias = (const float*)d_in[2];
    const float* h    = (const float*)d_in[3];
    const float* pw   = (const float*)d_in[4];
    float* out = (float*)d_out;

    int B = in_sizes[0] / (FEAT * EDIM);
    size_t smem_bytes = sizeof(Smem);

    static bool attr_set = false;
    if (!attr_set) {
        cudaFuncSetAttribute(afm_main_kernel,
                             cudaFuncAttributeMaxDynamicSharedMemorySize,
                             (int)smem_bytes);
        attr_set = true;
    }

    prep_kernel<<<1, 288>>>(W, pw);
    afm_main_kernel<<<B, NT, smem_bytes>>>(x, bias, h, out);
}

// round 16
// speedup vs baseline: 1.3339x; 1.0828x over previous
#include <cuda_runtime.h>
#include <cuda_fp16.h>
#include <cstdint>
#include <cstring>

#define FEAT   40
#define EDIM   64
#define ADIM   64
#define NB     9            // n-blocks: 8 for W (64 cols) + 1 for pw column
#define NPAIR  780
#define NSLOT  800          // table size (50 blocks x 16); slots 784+ unused
#define NSLOT_R 784         // real sweep range: blocks 0..48
#define NPPAIR 24           // perfectly balanced block-pairs (blocks 0..47)
#define NT     256
#define XS_STRIDE 80        // adjacent rows bank-disjoint
#define NFRAG  (4 * NB * 32)

// ---------------------------------------------------------------------------
// m16n8k16 fp16 MMA with f32 accumulation (arch-generic, works on sm_100)
// ---------------------------------------------------------------------------
__device__ __forceinline__ void mma_fp16(float d[4],
                                         uint32_t a0, uint32_t a1,
                                         uint32_t a2, uint32_t a3,
                                         uint32_t b0, uint32_t b1) {
    asm volatile(
        "mma.sync.aligned.m16n8k16.row.col.f32.f16.f16.f32 "
        "{%0,%1,%2,%3}, {%4,%5,%6,%7}, {%8,%9}, {%0,%1,%2,%3};"
        : "+f"(d[0]), "+f"(d[1]), "+f"(d[2]), "+f"(d[3])
        : "r"(a0), "r"(a1), "r"(a2), "r"(a3), "r"(b0), "r"(b1));
}

__device__ __forceinline__ uint32_t h2u(__half2 h) {
    uint32_t u;
    memcpy(&u, &h, 4);
    return u;
}

// Precomputed W' fragments + grid-blocked slot->(i,j) tables, built once.
__device__ uint2 g_Whf[NFRAG];
__device__ unsigned char g_bi[NSLOT];
__device__ unsigned char g_bj[NSLOT];

__global__ void prep_kernel(const float* __restrict__ W,
                            const float* __restrict__ pw) {
    const int tid = threadIdx.x;
    for (int idx = tid; idx < NFRAG; idx += 512) {
        int l    = idx & 31;
        int nblk = (idx >> 5) % NB;
        int eblk = (idx >> 5) / NB;
        int n  = 8 * nblk + (l >> 2);
        int k0 = 16 * eblk + (l & 3) * 2;
        float w00, w01, w10, w11;
        if (n < ADIM) {
            w00 = W[(k0    ) * ADIM + n];
            w01 = W[(k0 + 1) * ADIM + n];
            w10 = W[(k0 + 8) * ADIM + n];
            w11 = W[(k0 + 9) * ADIM + n];
        } else if (n == ADIM) {           // the pw column
            w00 = pw[k0];     w01 = pw[k0 + 1];
            w10 = pw[k0 + 8]; w11 = pw[k0 + 9];
        } else {                           // zero padding cols 65..71
            w00 = w01 = w10 = w11 = 0.f;
        }
        g_Whf[idx] = make_uint2(h2u(__floats2half2_rn(w00, w01)),
                                h2u(__floats2half2_rn(w10, w11)));
    }
    // Parallel pair-table build (was serial on thread 0):
    // slots [0,720): 45 cross blocks (4x4 grids); [720,780): intra pairs;
    // [780,800): dummy (255).
    for (int t = tid; t < NSLOT; t += 512) {
        unsigned char bi, bj;
        if (t < 720) {
            int p = t >> 4, q = t & 15;
            int g0 = 0, rem = p;
            while (rem >= 9 - g0) { rem -= 9 - g0; g0++; }
            int g1 = g0 + 1 + rem;
            bi = (unsigned char)(4 * g0 + (q >> 2));
            bj = (unsigned char)(4 * g1 + (q & 3));
        } else if (t < 780) {
            int u = t - 720;
            int g = u / 6, rm = u % 6;
            const int ia[6] = {0, 0, 0, 1, 1, 2};
            const int ja[6] = {1, 2, 3, 2, 3, 3};
            bi = (unsigned char)(4 * g + ia[rm]);
            bj = (unsigned char)(4 * g + ja[rm]);
        } else { bi = 255; bj = 0; }
        g_bi[t] = bi;
        g_bj[t] = bj;
    }
}

struct __align__(16) Smem {
    float xs[FEAT * XS_STRIDE];   // 12800  e-PERMUTED x rows
    uint2 Whf[NFRAG];             // 9216
    float sc[NSLOT];              // 3200
    float sq[NSLOT];              // 3200
    float bs[ADIM];
    float hs[ADIM];
    float redm[8];
    float reds[8];
    float redd[8];
    unsigned char bi[NSLOT];
    unsigned char bj[NSLOT];
};

__global__ __launch_bounds__(NT, 4)
void afm_main_kernel(const float* __restrict__ x,
                     const float* __restrict__ bias,
                     const float* __restrict__ h,
                     float* __restrict__ out) {
    extern __shared__ char smem_raw[];
    Smem* s = reinterpret_cast<Smem*>(smem_raw);

    const int b    = blockIdx.x;
    const int tid  = threadIdx.x;
    const int wid  = tid >> 5;
    const int lane = tid & 31;

    // ---------------- Phase 0: coalesced staging (xs e-permuted) --------
    {
        const float* xb = x + (long)b * FEAT * EDIM;
        for (int idx = tid; idx < FEAT * EDIM; idx += NT) {
            int row = idx >> 6, col = idx & 63;
            int bl = col & 15;
            int newb = ((bl & 6) << 1) | ((bl >> 3) << 1) | (bl & 1);
            s->xs[row * XS_STRIDE + (col & ~15) + newb] = xb[idx];
        }
        const uint4* src = (const uint4*)g_Whf;     // 576 uint4
        uint4* dst = (uint4*)s->Whf;
        for (int i = tid; i < 576; i += NT) dst[i] = src[i];
        {   // slot tables: 2 x 50 uint4
            const uint4* pi = (const uint4*)g_bi;
            const uint4* pj = (const uint4*)g_bj;
            uint4* di = (uint4*)s->bi;
            uint4* dj = (uint4*)s->bj;
            if (tid < 50) di[tid] = pi[tid];
            else if (tid < 100) dj[tid - 50] = pj[tid - 50];
        }
        if (tid < ADIM) { s->bs[tid] = bias[tid]; s->hs[tid] = h[tid]; }
    }
    __syncthreads();

    const int r  = lane >> 2;          // row-within-16 (0..7)
    const int c0 = (lane & 3) * 2;     // col pair base (epilogue)
    const int t4 = (lane & 3) * 4;     // permuted k-group offset (A-build)

    // ---------------- Phase 1a: 24 balanced block-pairs (3 per warp) ----
    for (int pt = wid; pt < NPPAIR; pt += 8) {
        const int slotA = (2 * pt)     * 16;
        const int slotB = (2 * pt + 1) * 16;

        const int ivA0 = s->bi[slotA + r],     jvA0 = s->bj[slotA + r];
        const int ivA1 = s->bi[slotA + r + 8], jvA1 = s->bj[slotA + r + 8];
        const int ivB0 = s->bi[slotB + r],     jvB0 = s->bj[slotB + r];
        const int ivB1 = s->bi[slotB + r + 8], jvB1 = s->bj[slotB + r + 8];
        const int oIA0 = ivA0 * XS_STRIDE, oJA0 = jvA0 * XS_STRIDE;
        const int oIA1 = ivA1 * XS_STRIDE, oJA1 = jvA1 * XS_STRIDE;
        const int oIB0 = ivB0 * XS_STRIDE, oJB0 = jvB0 * XS_STRIDE;
        const int oIB1 = ivB1 * XS_STRIDE, oJB1 = jvB1 * XS_STRIDE;

        // --- build A fragments for BOTH blocks, all 4 eb ---
        uint32_t aA[4][4], aB[4][4];
        #pragma unroll
        for (int eb = 0; eb < 4; eb++) {
            const int e4 = 16 * eb + t4;
            {
                float4 xi = *(const float4*)(s->xs + oIA0 + e4);
                float4 xj = *(const float4*)(s->xs + oJA0 + e4);
                aA[eb][0] = h2u(__floats2half2_rn(xi.x * xj.x, xi.y * xj.y));
                aA[eb][2] = h2u(__floats2half2_rn(xi.z * xj.z, xi.w * xj.w));
            }
            {
                float4 xi = *(const float4*)(s->xs + oIA1 + e4);
                float4 xj = *(const float4*)(s->xs + oJA1 + e4);
                aA[eb][1] = h2u(__floats2half2_rn(xi.x * xj.x, xi.y * xj.y));
                aA[eb][3] = h2u(__floats2half2_rn(xi.z * xj.z, xi.w * xj.w));
            }
            {
                float4 xi = *(const float4*)(s->xs + oIB0 + e4);
                float4 xj = *(const float4*)(s->xs + oJB0 + e4);
                aB[eb][0] = h2u(__floats2half2_rn(xi.x * xj.x, xi.y * xj.y));
                aB[eb][2] = h2u(__floats2half2_rn(xi.z * xj.z, xi.w * xj.w));
            }
            {
                float4 xi = *(const float4*)(s->xs + oIB1 + e4);
                float4 xj = *(const float4*)(s->xs + oJB1 + e4);
                aB[eb][1] = h2u(__floats2half2_rn(xi.x * xj.x, xi.y * xj.y));
                aB[eb][3] = h2u(__floats2half2_rn(xi.z * xj.z, xi.w * xj.w));
            }
        }

        // --- nb-outer loop: 8-reg accumulators, fused per-nb epilogue ---
        float sA0 = 0.f, sA1 = 0.f, sB0 = 0.f, sB1 = 0.f;
        float qA0 = 0.f, qA1 = 0.f, qB0 = 0.f, qB1 = 0.f;
        #pragma unroll
        for (int nb = 0; nb < NB; nb++) {
            float b0v = 0.f, b1v = 0.f;
            if (nb < 8) { b0v = s->bs[8 * nb + c0]; b1v = s->bs[8 * nb + c0 + 1]; }
            float d0[4] = {b0v, b1v, b0v, b1v};
            float d1[4] = {b0v, b1v, b0v, b1v};
            #pragma unroll
            for (int eb = 0; eb < 4; eb++) {
                uint2 bf = s->Whf[(eb * NB + nb) * 32 + lane];
                mma_fp16(d0, aA[eb][0], aA[eb][1], aA[eb][2], aA[eb][3],
                         bf.x, bf.y);
                mma_fp16(d1, aB[eb][0], aB[eb][1], aB[eb][2], aB[eb][3],
                         bf.x, bf.y);
            }
            if (nb < 8) {
                float h0v = s->hs[8 * nb + c0], h1v = s->hs[8 * nb + c0 + 1];
                sA0 = fmaf(fmaxf(d0[0], 0.f), h0v, sA0);
                sA0 = fmaf(fmaxf(d0[1], 0.f), h1v, sA0);
                sA1 = fmaf(fmaxf(d0[2], 0.f), h0v, sA1);
                sA1 = fmaf(fmaxf(d0[3], 0.f), h1v, sA1);
                sB0 = fmaf(fmaxf(d1[0], 0.f), h0v, sB0);
                sB0 = fmaf(fmaxf(d1[1], 0.f), h1v, sB0);
                sB1 = fmaf(fmaxf(d1[2], 0.f), h0v, sB1);
                sB1 = fmaf(fmaxf(d1[3], 0.f), h1v, sB1);
            } else {
                qA0 = d0[0]; qA1 = d0[2];
                qB0 = d1[0]; qB1 = d1[2];
            }
        }

        sA0 += __shfl_xor_sync(0xffffffffu, sA0, 1);
        sA0 += __shfl_xor_sync(0xffffffffu, sA0, 2);
        sA1 += __shfl_xor_sync(0xffffffffu, sA1, 1);
        sA1 += __shfl_xor_sync(0xffffffffu, sA1, 2);
        sB0 += __shfl_xor_sync(0xffffffffu, sB0, 1);
        sB0 += __shfl_xor_sync(0xffffffffu, sB0, 2);
        sB1 += __shfl_xor_sync(0xffffffffu, sB1, 1);
        sB1 += __shfl_xor_sync(0xffffffffu, sB1, 2);
        if ((lane & 3) == 0) {
            s->sc[slotA + r]     = sA0;
            s->sq[slotA + r]     = qA0;
            s->sc[slotA + r + 8] = sA1;
            s->sq[slotA + r + 8] = qA1;
            s->sc[slotB + r]     = sB0;
            s->sq[slotB + r]     = qB0;
            s->sc[slotB + r + 8] = sB1;
            s->sq[slotB + r + 8] = qB1;
        }
    }

    // ---------------- Phase 1b: single leftover block 48 (warp 7) -------
    if (wid == 7) {
        const int slotA = 48 * 16;     // slots 768..783 (780..783 dummy)
        const int ivA0 = s->bi[slotA + r],     jvA0 = s->bj[slotA + r];
        const int ivA1 = s->bi[slotA + r + 8], jvA1 = s->bj[slotA + r + 8];
        const bool vA0 = (ivA0 != 255);
        const bool vA1 = (ivA1 != 255);
        const int oIA0 = (vA0 ? ivA0 : 0) * XS_STRIDE, oJA0 = jvA0 * XS_STRIDE;
        const int oIA1 = (vA1 ? ivA1 : 0) * XS_STRIDE, oJA1 = jvA1 * XS_STRIDE;

        uint32_t aA[4][4];
        #pragma unroll
        for (int eb = 0; eb < 4; eb++) {
            const int e4 = 16 * eb + t4;
            {
                float4 xi = *(const float4*)(s->xs + oIA0 + e4);
                float4 xj = *(const float4*)(s->xs + oJA0 + e4);
                aA[eb][0] = h2u(__floats2half2_rn(xi.x * xj.x, xi.y * xj.y));
                aA[eb][2] = h2u(__floats2half2_rn(xi.z * xj.z, xi.w * xj.w));
            }
            {
                float4 xi = *(const float4*)(s->xs + oIA1 + e4);
                float4 xj = *(const float4*)(s->xs + oJA1 + e4);
                aA[eb][1] = h2u(__floats2half2_rn(xi.x * xj.x, xi.y * xj.y));
                aA[eb][3] = h2u(__floats2half2_rn(xi.z * xj.z, xi.w * xj.w));
            }
        }

        float sA0 = 0.f, sA1 = 0.f, qA0 = 0.f, qA1 = 0.f;
        #pragma unroll
        for (int nb = 0; nb < NB; nb++) {
            float b0v = 0.f, b1v = 0.f;
            if (nb < 8) { b0v = s->bs[8 * nb + c0]; b1v = s->bs[8 * nb + c0 + 1]; }
            float d0[4] = {b0v, b1v, b0v, b1v};
            #pragma unroll
            for (int eb = 0; eb < 4; eb++) {
                uint2 bf = s->Whf[(eb * NB + nb) * 32 + lane];
                mma_fp16(d0, aA[eb][0], aA[eb][1], aA[eb][2], aA[eb][3],
                         bf.x, bf.y);
            }
            if (nb < 8) {
                float h0v = s->hs[8 * nb + c0], h1v = s->hs[8 * nb + c0 + 1];
                sA0 = fmaf(fmaxf(d0[0], 0.f), h0v, sA0);
                sA0 = fmaf(fmaxf(d0[1], 0.f), h1v, sA0);
                sA1 = fmaf(fmaxf(d0[2], 0.f), h0v, sA1);
                sA1 = fmaf(fmaxf(d0[3], 0.f), h1v, sA1);
            } else {
                qA0 = d0[0]; qA1 = d0[2];
            }
        }
        sA0 += __shfl_xor_sync(0xffffffffu, sA0, 1);
        sA0 += __shfl_xor_sync(0xffffffffu, sA0, 2);
        sA1 += __shfl_xor_sync(0xffffffffu, sA1, 1);
        sA1 += __shfl_xor_sync(0xffffffffu, sA1, 2);
        if ((lane & 3) == 0) {
            s->sc[slotA + r]     = vA0 ? sA0 : -1e30f;
            s->sq[slotA + r]     = vA0 ? qA0 : 0.f;
            s->sc[slotA + r + 8] = vA1 ? sA1 : -1e30f;
            s->sq[slotA + r + 8] = vA1 ? qA1 : 0.f;
        }
    }
    __syncthreads();

    // ---------------- Phase 2: fused softmax + weighted dot -------------
    float m = -3.402823466e38f;
    for (int p = tid; p < NSLOT_R; p += NT) m = fmaxf(m, s->sc[p]);
    #pragma unroll
    for (int o = 16; o; o >>= 1) m = fmaxf(m, __shfl_xor_sync(0xffffffffu, m, o));
    if (lane == 0) s->redm[wid] = m;
    __syncthreads();
    if (tid == 0) {
        float mm = s->redm[0];
        #pragma unroll
        for (int w = 1; w < 8; w++) mm = fmaxf(mm, s->redm[w]);
        s->redm[0] = mm;
    }
    __syncthreads();
    m = s->redm[0];

    float sum = 0.f, dot = 0.f;
    for (int p = tid; p < NSLOT_R; p += NT) {
        float e0 = __expf(s->sc[p] - m);      // dummies -> 0
        sum += e0;
        dot = fmaf(e0, s->sq[p], dot);
    }
    #pragma unroll
    for (int o = 16; o; o >>= 1) {
        sum += __shfl_xor_sync(0xffffffffu, sum, o);
        dot += __shfl_xor_sync(0xffffffffu, dot, o);
    }
    if (lane == 0) { s->reds[wid] = sum; s->redd[wid] = dot; }
    __syncthreads();
    if (tid == 0) {
        float ss = s->reds[0], dd = s->redd[0];
        #pragma unroll
        for (int w = 1; w < 8; w++) { ss += s->reds[w]; dd += s->redd[w]; }
        out[b] = (float)NPAIR * dd / ss;
    }
}

extern "C" void kernel_launch(void* const* d_in, const int* in_sizes, int n_in,
                              void* d_out, int out_size) {
    const float* x    = (const float*)d_in[0];
    const float* W    = (const float*)d_in[1];
    const float* bias = (const float*)d_in[2];
    const float* h    = (const float*)d_in[3];
    const float* pw   = (const float*)d_in[4];
    float* out = (float*)d_out;

    int B = in_sizes[0] / (FEAT * EDIM);
    size_t smem_bytes = sizeof(Smem);

    static bool attr_set = false;
    if (!attr_set) {
        cudaFuncSetAttribute(afm_main_kernel,
                             cudaFuncAttributeMaxDynamicSharedMemorySize,
                             (int)smem_bytes);
        attr_set = true;
    }

    prep_kernel<<<1, 512>>>(W, pw);
    afm_main_kernel<<<B, NT, smem_bytes>>>(x, bias, h, out);
}